// round 10
// baseline (speedup 1.0000x reference)
#include <cuda_runtime.h>
#include <cstdint>

// CRPS over a 16-member ensemble:
//   out = mean_p( (1/N) sum_i |s_i - y|  -  (1/N^2) sum_{i<j} |s_i - s_j| )
// Identity: with v sorted ascending, sum_{i<j}|v_i - v_j| = sum_i (2i-15) v_i.
//
// R10: cp.async.bulk (TMA engine) loader. Seven LDG/LDGSTS variants all
// plateaued at ~2 TB/s == ~40 outstanding lines/SM: the per-SM load-tracking
// pool is the ceiling, independent of issue order/registers/occupancy.
// Bulk copies are tracked in the TMA unit, not the SM's LDG queue, so the
// stream depth decouples from the SM. 17 x 1KB bulk copies per 17KB tile,
// two tiles per block, both posted before compute; mbarrier completion.

#define NS 16
#define PIXELS (4 * 1 * 256 * 256)      // 262144
#define TPB 256
#define TILE 256                        // pixels per tile (== TPB)
#define TILES_PER_BLK 2
#define NBLOCKS (PIXELS / (TILE * TILES_PER_BLK))   // 512
#define TILE_WORDS (NS * TILE + TILE)   // 4352 floats = 17408 B
#define TILE_BYTES (TILE_WORDS * 4)
#define ROW_BYTES (TILE * 4)            // 1024 B per member row

__device__ float g_partials[NBLOCKS];
__device__ unsigned int g_count = 0;

__device__ __forceinline__ void cmpswap(float& a, float& b) {
    float lo = fminf(a, b);
    float hi = fmaxf(a, b);
    a = lo; b = hi;
}

__device__ __forceinline__ unsigned smem_u32(const void* p) {
    return (unsigned)__cvta_generic_to_shared(p);
}

__device__ __forceinline__ void mbar_init(unsigned mbar, unsigned count) {
    asm volatile("mbarrier.init.shared::cta.b64 [%0], %1;" :: "r"(mbar), "r"(count) : "memory");
}
__device__ __forceinline__ void mbar_expect_tx(unsigned mbar, unsigned bytes) {
    asm volatile("mbarrier.arrive.expect_tx.shared::cta.b64 _, [%0], %1;"
                 :: "r"(mbar), "r"(bytes) : "memory");
}
__device__ __forceinline__ void bulk_g2s(unsigned dst, const void* src,
                                         unsigned bytes, unsigned mbar) {
    asm volatile(
        "cp.async.bulk.shared::cluster.global.mbarrier::complete_tx::bytes "
        "[%0], [%1], %2, [%3];"
        :: "r"(dst), "l"(src), "r"(bytes), "r"(mbar) : "memory");
}
__device__ __forceinline__ void mbar_wait(unsigned mbar, unsigned parity) {
    asm volatile(
        "{\n\t"
        ".reg .pred P;\n\t"
        "WAIT_%=: \n\t"
        "mbarrier.try_wait.parity.acquire.cta.shared::cta.b64 P, [%0], %1, 0x989680;\n\t"
        "@P bra.uni DONE_%=;\n\t"
        "bra.uni WAIT_%=;\n\t"
        "DONE_%=: \n\t"
        "}"
        :: "r"(mbar), "r"(parity) : "memory");
}

// Per-pixel CRPS contribution from a smem tile (member i at buf[i*TILE + tid]).
__device__ __forceinline__ float crps_from_tile(const float* buf, int tid) {
    float v[NS];
#pragma unroll
    for (int i = 0; i < NS; i++)
        v[i] = buf[i * TILE + tid];
    const float y = buf[NS * TILE + tid];

    float t1 = 0.f;
#pragma unroll
    for (int i = 0; i < NS; i++)
        t1 += fabsf(v[i] - y);

    // Batcher odd-even mergesort, 16 inputs, 63 comparators.
#define CS(a, b) cmpswap(v[a], v[b])
    CS(0,1);  CS(2,3);  CS(4,5);  CS(6,7);  CS(8,9);  CS(10,11); CS(12,13); CS(14,15);
    CS(0,2);  CS(1,3);  CS(4,6);  CS(5,7);  CS(8,10); CS(9,11);  CS(12,14); CS(13,15);
    CS(1,2);  CS(5,6);  CS(9,10); CS(13,14);
    CS(0,4);  CS(1,5);  CS(2,6);  CS(3,7);  CS(8,12); CS(9,13);  CS(10,14); CS(11,15);
    CS(2,4);  CS(3,5);  CS(10,12); CS(11,13);
    CS(1,2);  CS(3,4);  CS(5,6);  CS(9,10); CS(11,12); CS(13,14);
    CS(0,8);  CS(1,9);  CS(2,10); CS(3,11); CS(4,12); CS(5,13);  CS(6,14);  CS(7,15);
    CS(4,8);  CS(5,9);  CS(6,10); CS(7,11);
    CS(2,4);  CS(3,5);  CS(6,8);  CS(7,9);  CS(10,12); CS(11,13);
    CS(1,2);  CS(3,4);  CS(5,6);  CS(7,8);  CS(9,10);  CS(11,12); CS(13,14);
#undef CS

    float t2 = 0.f;
#pragma unroll
    for (int i = 0; i < NS; i++)
        t2 = fmaf((float)(2 * i - 15), v[i], t2);

    return t1 * (1.f / NS) - t2 * (1.f / (NS * NS));
}

__global__ __launch_bounds__(TPB) void crps_fused_kernel(
    const float* __restrict__ samples,   // [NS, PIXELS]
    const float* __restrict__ target,    // [PIXELS]
    float* __restrict__ out)
{
    __shared__ __align__(128) float sbuf[TILES_PER_BLK][TILE_WORDS];  // 34,816 B
    __shared__ __align__(8) unsigned long long mbar_storage[TILES_PER_BLK];

    const int tid = threadIdx.x;
    const int tile0 = blockIdx.x * TILES_PER_BLK;

    unsigned mbar[TILES_PER_BLK];
#pragma unroll
    for (int k = 0; k < TILES_PER_BLK; k++)
        mbar[k] = smem_u32(&mbar_storage[k]);

    if (tid == 0) {
#pragma unroll
        for (int k = 0; k < TILES_PER_BLK; k++)
            mbar_init(mbar[k], 1);
    }
    __syncthreads();

    // Post ALL bulk copies up front: 2 tiles x (16 members + target) x 1KB.
    if (tid == 0) {
#pragma unroll
        for (int k = 0; k < TILES_PER_BLK; k++) {
            const int px = (tile0 + k) * TILE;
            mbar_expect_tx(mbar[k], TILE_BYTES);
            unsigned dst = smem_u32(&sbuf[k][0]);
#pragma unroll
            for (int i = 0; i < NS; i++)
                bulk_g2s(dst + i * ROW_BYTES, samples + i * PIXELS + px,
                         ROW_BYTES, mbar[k]);
            bulk_g2s(dst + NS * ROW_BYTES, target + px, ROW_BYTES, mbar[k]);
        }
    }

    float acc = 0.f;
#pragma unroll
    for (int k = 0; k < TILES_PER_BLK; k++) {
        mbar_wait(mbar[k], 0);
        acc += crps_from_tile(sbuf[k], tid);
    }

    // ---- block reduction ----
#pragma unroll
    for (int off = 16; off > 0; off >>= 1)
        acc += __shfl_down_sync(0xFFFFFFFFu, acc, off);

    __shared__ float warp_sums[TPB / 32];
    const int lane = tid & 31;
    const int wid  = tid >> 5;
    if (lane == 0) warp_sums[wid] = acc;
    __syncthreads();

    __shared__ bool is_last;
    if (tid == 0) {
        float bsum = 0.f;
#pragma unroll
        for (int w = 0; w < TPB / 32; w++)
            bsum += warp_sums[w];
        g_partials[blockIdx.x] = bsum;
        __threadfence();
        unsigned int done = atomicAdd(&g_count, 1u);
        is_last = (done == NBLOCKS - 1);
    }
    __syncthreads();

    // ---- last block folds all 512 partials in a fixed order ----
    if (is_last) {
        float s = g_partials[tid] + g_partials[tid + TPB];
#pragma unroll
        for (int off = 16; off > 0; off >>= 1)
            s += __shfl_down_sync(0xFFFFFFFFu, s, off);
        if (lane == 0) warp_sums[wid] = s;
        __syncthreads();
        if (wid == 0) {
            float tot = (lane < TPB / 32) ? warp_sums[lane] : 0.f;
#pragma unroll
            for (int off = 4; off > 0; off >>= 1)
                tot += __shfl_down_sync(0xFFFFFFFFu, tot, off);
            if (lane == 0) {
                out[0] = tot * (1.f / PIXELS);
                g_count = 0;   // reset for next graph replay
            }
        }
    }
}

extern "C" void kernel_launch(void* const* d_in, const int* in_sizes, int n_in,
                              void* d_out, int out_size)
{
    const float* samples = (const float*)d_in[0];
    const float* target  = (const float*)d_in[1];
    float* out = (float*)d_out;

    crps_fused_kernel<<<NBLOCKS, TPB>>>(samples, target, out);
}